// round 5
// baseline (speedup 1.0000x reference)
#include <cuda_runtime.h>
#include <cuda_fp16.h>
#include <cstdint>

#define HW (128*128)

// ---------------- scratch (no allocations allowed) ----------------
__device__ float  g_om[8*27*HW];          // conv1 out: offsets raw, mask = 2*sigmoid
__device__ float  g_xt[8*HW*64];          // x transposed to NHWC [b][pix][c]
__device__ __half g_wdc_h[9*2*4096];      // [kf][hi/lo][oc(64)][c(64)]
__device__ __half g_wom_h[9*2*2048];      // [kf][hi/lo][oc(32, 27 used)][c(64)]

// ---------------- helpers ----------------
__device__ __forceinline__ uint32_t smem_u32(const void* p){
    uint32_t a;
    asm("{ .reg .u64 t; cvta.to.shared.u64 t, %1; cvt.u32.u64 %0, t; }" : "=r"(a) : "l"(p));
    return a;
}
__device__ __forceinline__ void ldsm_x4(uint32_t &r0,uint32_t &r1,uint32_t &r2,uint32_t &r3, uint32_t addr){
    asm volatile("ldmatrix.sync.aligned.m8n8.x4.shared.b16 {%0,%1,%2,%3}, [%4];"
        : "=r"(r0),"=r"(r1),"=r"(r2),"=r"(r3) : "r"(addr));
}
__device__ __forceinline__ void ldsm_x2(uint32_t &r0,uint32_t &r1, uint32_t addr){
    asm volatile("ldmatrix.sync.aligned.m8n8.x2.shared.b16 {%0,%1}, [%2];"
        : "=r"(r0),"=r"(r1) : "r"(addr));
}
__device__ __forceinline__ void mma16816(float* d, const uint32_t* a, const uint32_t* b){
    asm volatile("mma.sync.aligned.m16n8k16.row.col.f32.f16.f16.f32 "
        "{%0,%1,%2,%3}, {%4,%5,%6,%7}, {%8,%9}, {%0,%1,%2,%3};"
        : "+f"(d[0]),"+f"(d[1]),"+f"(d[2]),"+f"(d[3])
        : "r"(a[0]),"r"(a[1]),"r"(a[2]),"r"(a[3]), "r"(b[0]),"r"(b[1]));
}
__device__ __forceinline__ uint32_t pack_hi(float a, float b, float &ra, float &rb){
    __half ha = __float2half_rn(a), hb = __float2half_rn(b);
    ra = a - __half2float(ha); rb = b - __half2float(hb);
    __half2 h2 = __halves2half2(ha, hb);
    return *(uint32_t*)&h2;
}
__device__ __forceinline__ uint32_t pack_lo(float ra, float rb){
    __half2 l2 = __floats2half2_rn(ra, rb);
    return *(uint32_t*)&l2;
}
__device__ __forceinline__ void fma4(float4 &acc, float w, float4 p){
    acc.x += w*p.x; acc.y += w*p.y; acc.z += w*p.z; acc.w += w*p.w;
}

__constant__ int cKY[9] = {-1,-1,-1, 0,0,0, 1,1,1};
__constant__ int cKX[9] = {-1, 0, 1,-1,0,1,-1,0,1};

// ---------------- kernel 0: weight split fp32 -> f16 hi/lo ----------------
__global__ void prep_kernel(const float* __restrict__ w_om, const float* __restrict__ w_dc){
    int i = blockIdx.x * blockDim.x + threadIdx.x;
    if (i < 9*4096){                     // deform: kf, oc(64), c(64)
        int kf = i >> 12, rem = i & 4095;
        int oc = rem >> 6, c = rem & 63;
        float w = w_dc[(oc*64 + c)*9 + kf];
        __half hi = __float2half_rn(w);
        __half lo = __float2half_rn(w - __half2float(hi));
        g_wdc_h[kf*8192 + rem]        = hi;
        g_wdc_h[kf*8192 + 4096 + rem] = lo;
    }
    int j = i - 9*4096;
    if (j >= 0 && j < 9*2048){           // conv1: kf, oc(32), c(64)
        int kf = j >> 11, rem = j & 2047;
        int oc = rem >> 6, c = rem & 63;
        float w = (oc < 27) ? w_om[(oc*64 + c)*9 + kf] : 0.f;
        __half hi = __float2half_rn(w);
        __half lo = __float2half_rn(w - __half2float(hi));
        g_wom_h[kf*4096 + rem]        = hi;
        g_wom_h[kf*4096 + 2048 + rem] = lo;
    }
}

// ---------------- kernel 0b: NCHW -> NHWC transpose ----------------
// block = 64 px x 64 ch tile, 256 threads, grid (256 px-tiles, 8 batch)
__global__ void __launch_bounds__(256)
transpose_kernel(const float* __restrict__ x){
    __shared__ float tile[64][65];
    const int b   = blockIdx.y;
    const int px0 = blockIdx.x * 64;
    const int t   = threadIdx.x;
    const float* xb = x + (size_t)b*64*HW + px0;
    {
        int cr = t >> 4, pq = t & 15;
        #pragma unroll
        for (int i = 0; i < 4; ++i){
            int c = i*16 + cr;
            float4 v = *(const float4*)(xb + (size_t)c*HW + pq*4);
            tile[c][pq*4+0]=v.x; tile[c][pq*4+1]=v.y;
            tile[c][pq*4+2]=v.z; tile[c][pq*4+3]=v.w;
        }
    }
    __syncthreads();
    {
        int px = t >> 2, cq = t & 3;
        float* ob = g_xt + ((size_t)b*HW + px0 + px)*64 + cq*16;
        #pragma unroll
        for (int i = 0; i < 4; ++i){
            int c = cq*16 + i*4;
            ((float4*)ob)[i] = make_float4(tile[c][px], tile[c+1][px],
                                           tile[c+2][px], tile[c+3][px]);
        }
    }
}

// =====================================================================
// smem tile geometry: rows padded to 72 halves (144 B) for conflict-free
// ldmatrix (stride = 9 x 16B -> 8 consecutive rows hit distinct 16B cols)
// =====================================================================
#define RSTRIDE 144

// conv stage: Xhi[128px][72h] 18432 | Xlo 18432 | Whi[32][72h] 4608 | Wlo 4608
#define CV_XHI  0
#define CV_XLO  18432
#define CV_WHI  36864
#define CV_WLO  41472
#define CV_STG  46080
#define CV_SMEM (2*CV_STG)

// deform stage: Vhi 18432 | Vlo 18432 | Whi[64][72h] 9216 | Wlo 9216
#define DF_VHI  0
#define DF_VLO  18432
#define DF_WHI  36864
#define DF_WLO  46080
#define DF_STG  55296
#define DF_SMEM (2*DF_STG)

// shared GEMM core: A = values[128px][64c] hi/lo, B = W[n][64c] hi/lo.
template<int NC>
__device__ __forceinline__ void mma_tap(uint32_t stg, int vhi_off, int vlo_off,
                                        int whi_off, int wlo_off,
                                        int lane, int px0, float d[NC][4]){
    const int arow = px0 + (lane & 15);
    const int akof = (lane >> 4) * 16;
    const uint32_t aBaseHi = stg + vhi_off + arow*RSTRIDE + akof;
    const uint32_t aBaseLo = stg + vlo_off + arow*RSTRIDE + akof;
    const int brow = (lane & 7);
    const int bkof = ((lane >> 3) & 1) * 16;
    uint32_t ah[4][4], al[4][4];
    #pragma unroll
    for (int kc = 0; kc < 4; ++kc){
        ldsm_x4(ah[kc][0],ah[kc][1],ah[kc][2],ah[kc][3], aBaseHi + kc*32);
        ldsm_x4(al[kc][0],al[kc][1],al[kc][2],al[kc][3], aBaseLo + kc*32);
    }
    #pragma unroll
    for (int nc = 0; nc < NC; ++nc){
        uint32_t bh[4][2], bl[4][2];
        const uint32_t bRow = (nc*8 + brow)*RSTRIDE + bkof;
        #pragma unroll
        for (int kc = 0; kc < 4; ++kc){
            ldsm_x2(bh[kc][0], bh[kc][1], stg + whi_off + bRow + kc*32);
            ldsm_x2(bl[kc][0], bl[kc][1], stg + wlo_off + bRow + kc*32);
        }
        #pragma unroll
        for (int kc = 0; kc < 4; ++kc){
            mma16816(d[nc], ah[kc], bh[kc]);
            mma16816(d[nc], ah[kc], bl[kc]);
            mma16816(d[nc], al[kc], bh[kc]);
        }
    }
}

// pack 8 float4 (32 ch) into hi/lo smem rows at (px, ch0)
__device__ __forceinline__ void store_hilo(char* sg, int vhi, int vlo,
                                           int px, int ch0, const float4* acc){
    #pragma unroll
    for (int j = 0; j < 4; ++j){
        float4 a = acc[2*j], b = acc[2*j+1];
        float r0,r1,r2,r3,r4,r5,r6,r7;
        uint32_t h0 = pack_hi(a.x, a.y, r0, r1);
        uint32_t h1 = pack_hi(a.z, a.w, r2, r3);
        uint32_t h2 = pack_hi(b.x, b.y, r4, r5);
        uint32_t h3 = pack_hi(b.z, b.w, r6, r7);
        *(uint4*)(sg + vhi + px*RSTRIDE + (ch0 + 8*j)*2) =
            make_uint4(h0, h1, h2, h3);
        *(uint4*)(sg + vlo + px*RSTRIDE + (ch0 + 8*j)*2) =
            make_uint4(pack_lo(r0,r1), pack_lo(r2,r3), pack_lo(r4,r5), pack_lo(r6,r7));
    }
}

// =====================================================================
// kernel 1: 3x3 conv 64->27 (+2*sigmoid) via f16x3 mma.sync
// CTA = one image row, grid (128, 8), 256 threads (8 warps x 16 px).
// =====================================================================
__global__ void __launch_bounds__(256, 2)
conv_om_kernel(const float* __restrict__ b_om){
    extern __shared__ char smem[];
    const uint32_t sb = smem_u32(smem);
    const int b   = blockIdx.y;
    const int row = blockIdx.x;
    const int t   = threadIdx.x;
    const int w   = t >> 5, lane = t & 31;
    const int px  = t & 127;
    const int ch0 = (t >> 7) * 32;
    const float* xtb = g_xt + (size_t)b*HW*64;

    float d[4][4];
    #pragma unroll
    for (int i = 0; i < 4; ++i)
        #pragma unroll
        for (int k = 0; k < 4; ++k) d[i][k] = 0.f;

    auto gather = [&](int kf, int buf){
        char* sg = smem + buf*CV_STG;
        {
            const __half* src = g_wom_h + kf*4096;
            int oc = t >> 3, seg = t & 7;
            ((uint4*)(sg + CV_WHI + oc*RSTRIDE + seg*16))[0] = ((const uint4*)src)[t];
            ((uint4*)(sg + CV_WLO + oc*RSTRIDE + seg*16))[0] = ((const uint4*)(src + 2048))[t];
        }
        int yy = row + cKY[kf], xx = px + cKX[kf];
        bool ok = (yy >= 0 && yy < 128 && xx >= 0 && xx < 128);
        int idx = ok ? (yy*128 + xx) : 0;
        const float4* p = (const float4*)(xtb + (size_t)idx*64 + ch0);
        float4 acc[8];
        #pragma unroll
        for (int j = 0; j < 8; ++j){
            float4 v = p[j];
            if (!ok) v = make_float4(0.f,0.f,0.f,0.f);
            acc[j] = v;
        }
        store_hilo(sg, CV_XHI, CV_XLO, px, ch0, acc);
    };

    gather(0, 0);
    for (int s = 0; s < 9; ++s){
        __syncthreads();
        if (s < 8) gather(s + 1, (s + 1) & 1);
        mma_tap<4>(sb + (s & 1)*CV_STG, CV_XHI, CV_XLO, CV_WHI, CV_WLO,
                   lane, w*16, d);
    }

    const int g  = lane >> 2, t4 = lane & 3;
    float* dstb = g_om + (size_t)b*27*HW + row*128;
    #pragma unroll
    for (int nc = 0; nc < 4; ++nc){
        int oc0 = 8*nc + 2*t4;
        #pragma unroll
        for (int q = 0; q < 2; ++q){
            int oc = oc0 + q;
            if (oc >= 27) continue;
            float bv = b_om[oc];
            float v0 = d[nc][q]     + bv;
            float v1 = d[nc][q + 2] + bv;
            if (oc >= 18){
                v0 = 2.f/(1.f + __expf(-v0));
                v1 = 2.f/(1.f + __expf(-v1));
            }
            dstb[(size_t)oc*HW + w*16 + g]     = v0;
            dstb[(size_t)oc*HW + w*16 + g + 8] = v1;
        }
    }
}

// =====================================================================
// kernel 2: deformable conv 64->64 via f16x3 mma.sync
// CTA = one image row, grid (128, 8), 256 threads.
// =====================================================================
__global__ void __launch_bounds__(256, 2)
deform_kernel(const float* __restrict__ b_dc, float* __restrict__ out){
    extern __shared__ char smem[];
    const uint32_t sb = smem_u32(smem);
    const int b   = blockIdx.y;
    const int row = blockIdx.x;
    const int t   = threadIdx.x;
    const int w   = t >> 5, lane = t & 31;
    const int px  = t & 127;
    const int ch0 = (t >> 7) * 32;
    const int pix = row*128 + px;
    const float* xtb = g_xt + (size_t)b*HW*64;
    const float* omb = g_om + (size_t)b*27*HW;

    float d[8][4];
    #pragma unroll
    for (int i = 0; i < 8; ++i)
        #pragma unroll
        for (int k = 0; k < 4; ++k) d[i][k] = 0.f;

    auto gather = [&](int kf, int buf){
        char* sg = smem + buf*DF_STG;
        {
            const __half* src = g_wdc_h + kf*8192;
            #pragma unroll
            for (int p = 0; p < 2; ++p){
                int j = t + p*256;
                int oc = j >> 3, seg = j & 7;
                ((uint4*)(sg + DF_WHI + oc*RSTRIDE + seg*16))[0] = ((const uint4*)src)[j];
                ((uint4*)(sg + DF_WLO + oc*RSTRIDE + seg*16))[0] = ((const uint4*)(src + 4096))[j];
            }
        }
        float offy = omb[(size_t)(2*kf    )*HW + pix];
        float offx = omb[(size_t)(2*kf + 1)*HW + pix];
        float m    = omb[(size_t)(18 + kf )*HW + pix];
        float py = (float)(row + cKY[kf]) + offy;
        float pxf= (float)(px  + cKX[kf]) + offx;
        float y0f = floorf(py), x0f = floorf(pxf);
        float fy = py - y0f, fx = pxf - x0f;
        int y0 = (int)y0f, x0 = (int)x0f, y1 = y0 + 1, x1 = x0 + 1;
        float vy0 = (y0 >= 0 && y0 <= 127) ? 1.f : 0.f;
        float vy1 = (y1 >= 0 && y1 <= 127) ? 1.f : 0.f;
        float vx0 = (x0 >= 0 && x0 <= 127) ? 1.f : 0.f;
        float vx1 = (x1 >= 0 && x1 <= 127) ? 1.f : 0.f;
        float w00 = (1.f-fy)*(1.f-fx)*vy0*vx0*m;
        float w01 = (1.f-fy)*fx      *vy0*vx1*m;
        float w10 = fy*(1.f-fx)      *vy1*vx0*m;
        float w11 = fy*fx            *vy1*vx1*m;
        int cy0 = min(max(y0,0),127), cy1 = min(max(y1,0),127);
        int cx0 = min(max(x0,0),127), cx1 = min(max(x1,0),127);
        const float4* p00 = (const float4*)(xtb + (size_t)(cy0*128 + cx0)*64 + ch0);
        const float4* p01 = (const float4*)(xtb + (size_t)(cy0*128 + cx1)*64 + ch0);
        const float4* p10 = (const float4*)(xtb + (size_t)(cy1*128 + cx0)*64 + ch0);
        const float4* p11 = (const float4*)(xtb + (size_t)(cy1*128 + cx1)*64 + ch0);
        float4 acc[8];
        #pragma unroll
        for (int j = 0; j < 8; ++j){
            float4 a = make_float4(0.f,0.f,0.f,0.f);
            fma4(a, w00, p00[j]);
            fma4(a, w01, p01[j]);
            fma4(a, w10, p10[j]);
            fma4(a, w11, p11[j]);
            acc[j] = a;
        }
        store_hilo(sg, DF_VHI, DF_VLO, px, ch0, acc);
    };

    gather(0, 0);
    for (int s = 0; s < 9; ++s){
        __syncthreads();
        if (s < 8) gather(s + 1, (s + 1) & 1);
        mma_tap<8>(sb + (s & 1)*DF_STG, DF_VHI, DF_VLO, DF_WHI, DF_WLO,
                   lane, w*16, d);
    }

    const int g  = lane >> 2, t4 = lane & 3;
    float* dstb = out + (size_t)b*64*HW + row*128;
    #pragma unroll
    for (int nc = 0; nc < 8; ++nc){
        int oc0 = 8*nc + 2*t4;
        #pragma unroll
        for (int q = 0; q < 2; ++q){
            int oc = oc0 + q;
            float bv = b_dc[oc];
            dstb[(size_t)oc*HW + w*16 + g]     = d[nc][q]     + bv;
            dstb[(size_t)oc*HW + w*16 + g + 8] = d[nc][q + 2] + bv;
        }
    }
}

// ---------------- launch ----------------
extern "C" void kernel_launch(void* const* d_in, const int* in_sizes, int n_in,
                              void* d_out, int out_size){
    const float* x    = (const float*)d_in[0];
    const float* w_om = (const float*)d_in[1];
    const float* b_om = (const float*)d_in[2];
    const float* w_dc = (const float*)d_in[3];
    const float* b_dc = (const float*)d_in[4];
    float* out = (float*)d_out;

    cudaFuncSetAttribute(conv_om_kernel, cudaFuncAttributeMaxDynamicSharedMemorySize, CV_SMEM);
    cudaFuncSetAttribute(deform_kernel,  cudaFuncAttributeMaxDynamicSharedMemorySize, DF_SMEM);

    prep_kernel<<<216, 256>>>(w_om, w_dc);
    transpose_kernel<<<dim3(256, 8), 256>>>(x);
    conv_om_kernel<<<dim3(128, 8), 256, CV_SMEM>>>(b_om);
    deform_kernel <<<dim3(128, 8), 256, DF_SMEM>>>(b_dc, out);
}

// round 6
// speedup vs baseline: 1.9952x; 1.9952x over previous
#include <cuda_runtime.h>
#include <cuda_fp16.h>
#include <cstdint>

#define HW (128*128)

// ---------------- scratch (no allocations allowed) ----------------
__device__ float  g_om[8*27*HW];          // conv1 out: offsets raw, mask = 2*sigmoid
__device__ float  g_xt[8*HW*64];          // x transposed to NHWC [b][pix][c]
__device__ __half g_wdc_h[9*2*4096];      // [kf][hi/lo][oc(64)][c(64)]
__device__ __half g_wom_h[9*2*2048];      // [kf][hi/lo][oc(32, 27 used)][c(64)]

// ---------------- helpers ----------------
__device__ __forceinline__ uint32_t smem_u32(const void* p){
    uint32_t a;
    asm("{ .reg .u64 t; cvta.to.shared.u64 t, %1; cvt.u32.u64 %0, t; }" : "=r"(a) : "l"(p));
    return a;
}
__device__ __forceinline__ void ldsm_x4(uint32_t &r0,uint32_t &r1,uint32_t &r2,uint32_t &r3, uint32_t addr){
    asm volatile("ldmatrix.sync.aligned.m8n8.x4.shared.b16 {%0,%1,%2,%3}, [%4];"
        : "=r"(r0),"=r"(r1),"=r"(r2),"=r"(r3) : "r"(addr));
}
__device__ __forceinline__ void ldsm_x2(uint32_t &r0,uint32_t &r1, uint32_t addr){
    asm volatile("ldmatrix.sync.aligned.m8n8.x2.shared.b16 {%0,%1}, [%2];"
        : "=r"(r0),"=r"(r1) : "r"(addr));
}
__device__ __forceinline__ void mma16816(float* d, const uint32_t* a, const uint32_t* b){
    asm volatile("mma.sync.aligned.m16n8k16.row.col.f32.f16.f16.f32 "
        "{%0,%1,%2,%3}, {%4,%5,%6,%7}, {%8,%9}, {%0,%1,%2,%3};"
        : "+f"(d[0]),"+f"(d[1]),"+f"(d[2]),"+f"(d[3])
        : "r"(a[0]),"r"(a[1]),"r"(a[2]),"r"(a[3]), "r"(b[0]),"r"(b[1]));
}
__device__ __forceinline__ uint32_t pack_hi(float a, float b, float &ra, float &rb){
    __half ha = __float2half_rn(a), hb = __float2half_rn(b);
    ra = a - __half2float(ha); rb = b - __half2float(hb);
    __half2 h2 = __halves2half2(ha, hb);
    return *(uint32_t*)&h2;
}
__device__ __forceinline__ uint32_t pack_lo(float ra, float rb){
    __half2 l2 = __floats2half2_rn(ra, rb);
    return *(uint32_t*)&l2;
}
__device__ __forceinline__ void fma4(float4 &acc, float w, float4 p){
    acc.x += w*p.x; acc.y += w*p.y; acc.z += w*p.z; acc.w += w*p.w;
}

__constant__ int cKY[9] = {-1,-1,-1, 0,0,0, 1,1,1};
__constant__ int cKX[9] = {-1, 0, 1,-1,0,1,-1,0,1};

// ---------------- kernel 0: weight split fp32 -> f16 hi/lo ----------------
__global__ void prep_kernel(const float* __restrict__ w_om, const float* __restrict__ w_dc){
    int i = blockIdx.x * blockDim.x + threadIdx.x;
    if (i < 9*4096){                     // deform: kf, oc(64), c(64)
        int kf = i >> 12, rem = i & 4095;
        int oc = rem >> 6, c = rem & 63;
        float w = w_dc[(oc*64 + c)*9 + kf];
        __half hi = __float2half_rn(w);
        __half lo = __float2half_rn(w - __half2float(hi));
        g_wdc_h[kf*8192 + rem]        = hi;
        g_wdc_h[kf*8192 + 4096 + rem] = lo;
    }
    int j = i - 9*4096;
    if (j >= 0 && j < 9*2048){           // conv1: kf, oc(32), c(64)
        int kf = j >> 11, rem = j & 2047;
        int oc = rem >> 6, c = rem & 63;
        float w = (oc < 27) ? w_om[(oc*64 + c)*9 + kf] : 0.f;
        __half hi = __float2half_rn(w);
        __half lo = __float2half_rn(w - __half2float(hi));
        g_wom_h[kf*4096 + rem]        = hi;
        g_wom_h[kf*4096 + 2048 + rem] = lo;
    }
}

// ---------------- kernel 0b: NCHW -> NHWC transpose ----------------
__global__ void __launch_bounds__(256)
transpose_kernel(const float* __restrict__ x){
    __shared__ float tile[64][65];
    const int b   = blockIdx.y;
    const int px0 = blockIdx.x * 64;
    const int t   = threadIdx.x;
    const float* xb = x + (size_t)b*64*HW + px0;
    {
        int cr = t >> 4, pq = t & 15;
        #pragma unroll
        for (int i = 0; i < 4; ++i){
            int c = i*16 + cr;
            float4 v = *(const float4*)(xb + (size_t)c*HW + pq*4);
            tile[c][pq*4+0]=v.x; tile[c][pq*4+1]=v.y;
            tile[c][pq*4+2]=v.z; tile[c][pq*4+3]=v.w;
        }
    }
    __syncthreads();
    {
        int px = t >> 2, cq = t & 3;
        float* ob = g_xt + ((size_t)b*HW + px0 + px)*64 + cq*16;
        #pragma unroll
        for (int i = 0; i < 4; ++i){
            int c = cq*16 + i*4;
            ((float4*)ob)[i] = make_float4(tile[c][px], tile[c+1][px],
                                           tile[c+2][px], tile[c+3][px]);
        }
    }
}

// =====================================================================
// smem geometry: rows padded to 72 halves (144 B), conflict-free ldmatrix
// =====================================================================
#define RSTRIDE 144

#define CV_XHI  0
#define CV_XLO  18432
#define CV_WHI  36864
#define CV_WLO  41472
#define CV_STG  46080
#define CV_SMEM (2*CV_STG)

#define DF_VHI  0
#define DF_VLO  18432
#define DF_WHI  36864
#define DF_WLO  46080
#define DF_STG  55296
#define DF_SMEM (2*DF_STG)

template<int NC>
__device__ __forceinline__ void mma_tap(uint32_t stg, int vhi_off, int vlo_off,
                                        int whi_off, int wlo_off,
                                        int lane, int px0, float d[NC][4]){
    const int arow = px0 + (lane & 15);
    const int akof = (lane >> 4) * 16;
    const uint32_t aBaseHi = stg + vhi_off + arow*RSTRIDE + akof;
    const uint32_t aBaseLo = stg + vlo_off + arow*RSTRIDE + akof;
    const int brow = (lane & 7);
    const int bkof = ((lane >> 3) & 1) * 16;
    uint32_t ah[4][4], al[4][4];
    #pragma unroll
    for (int kc = 0; kc < 4; ++kc){
        ldsm_x4(ah[kc][0],ah[kc][1],ah[kc][2],ah[kc][3], aBaseHi + kc*32);
        ldsm_x4(al[kc][0],al[kc][1],al[kc][2],al[kc][3], aBaseLo + kc*32);
    }
    #pragma unroll
    for (int nc = 0; nc < NC; ++nc){
        uint32_t bh[4][2], bl[4][2];
        const uint32_t bRow = (nc*8 + brow)*RSTRIDE + bkof;
        #pragma unroll
        for (int kc = 0; kc < 4; ++kc){
            ldsm_x2(bh[kc][0], bh[kc][1], stg + whi_off + bRow + kc*32);
            ldsm_x2(bl[kc][0], bl[kc][1], stg + wlo_off + bRow + kc*32);
        }
        #pragma unroll
        for (int kc = 0; kc < 4; ++kc){
            mma16816(d[nc], ah[kc], bh[kc]);
            mma16816(d[nc], ah[kc], bl[kc]);
            mma16816(d[nc], al[kc], bh[kc]);
        }
    }
}

// =====================================================================
// kernel 1: 3x3 conv 64->27 (+2*sigmoid) via f16x3 mma.sync
// CTA = one image row, grid (128, 8), 256 threads.
// gather: warp = 2 px x 16 lanes; lane = 4-ch chunk (coalesced NHWC)
// =====================================================================
__global__ void __launch_bounds__(256, 2)
conv_om_kernel(const float* __restrict__ b_om){
    extern __shared__ char smem[];
    const uint32_t sb = smem_u32(smem);
    const int b   = blockIdx.y;
    const int row = blockIdx.x;
    const int t   = threadIdx.x;
    const int w   = t >> 5, lane = t & 31;
    const int sub = lane >> 4;       // pixel within warp pair
    const int ch  = (lane & 15) * 4; // channel chunk
    const float* xtb = g_xt + (size_t)b*HW*64;

    float d[4][4];
    #pragma unroll
    for (int i = 0; i < 4; ++i)
        #pragma unroll
        for (int k = 0; k < 4; ++k) d[i][k] = 0.f;

    auto gather = [&](int kf, int buf){
        char* sg = smem + buf*CV_STG;
        {
            const __half* src = g_wom_h + kf*4096;
            int oc = t >> 3, seg = t & 7;
            ((uint4*)(sg + CV_WHI + oc*RSTRIDE + seg*16))[0] = ((const uint4*)src)[t];
            ((uint4*)(sg + CV_WLO + oc*RSTRIDE + seg*16))[0] = ((const uint4*)(src + 2048))[t];
        }
        const int yy = row + cKY[kf];
        const bool okY = (yy >= 0 && yy < 128);
        #pragma unroll 2
        for (int p = 0; p < 8; ++p){
            int gpx = p*16 + w*2 + sub;
            int xx = gpx + cKX[kf];
            bool ok = okY && (xx >= 0 && xx < 128);
            float4 v = make_float4(0.f,0.f,0.f,0.f);
            if (ok) v = *(const float4*)(xtb + (size_t)(yy*128 + xx)*64 + ch);
            float r0,r1,r2,r3;
            uint32_t h0 = pack_hi(v.x, v.y, r0, r1);
            uint32_t h1 = pack_hi(v.z, v.w, r2, r3);
            *(uint2*)(sg + CV_XHI + gpx*RSTRIDE + ch*2) = make_uint2(h0, h1);
            *(uint2*)(sg + CV_XLO + gpx*RSTRIDE + ch*2) = make_uint2(pack_lo(r0,r1), pack_lo(r2,r3));
        }
    };

    gather(0, 0);
    for (int s = 0; s < 9; ++s){
        __syncthreads();
        if (s < 8) gather(s + 1, (s + 1) & 1);
        mma_tap<4>(sb + (s & 1)*CV_STG, CV_XHI, CV_XLO, CV_WHI, CV_WLO,
                   lane, w*16, d);
    }

    const int g  = lane >> 2, t4 = lane & 3;
    float* dstb = g_om + (size_t)b*27*HW + row*128;
    #pragma unroll
    for (int nc = 0; nc < 4; ++nc){
        int oc0 = 8*nc + 2*t4;
        #pragma unroll
        for (int q = 0; q < 2; ++q){
            int oc = oc0 + q;
            if (oc >= 27) continue;
            float bv = b_om[oc];
            float v0 = d[nc][q]     + bv;
            float v1 = d[nc][q + 2] + bv;
            if (oc >= 18){
                v0 = 2.f/(1.f + __expf(-v0));
                v1 = 2.f/(1.f + __expf(-v1));
            }
            dstb[(size_t)oc*HW + w*16 + g]     = v0;
            dstb[(size_t)oc*HW + w*16 + g + 8] = v1;
        }
    }
}

// =====================================================================
// kernel 2: deformable conv 64->64 via f16x3 mma.sync
// gather: warp = 2 px x 16 lanes, 4 coalesced corner LDG.128 per lane
// =====================================================================
__global__ void __launch_bounds__(256, 2)
deform_kernel(const float* __restrict__ b_dc, float* __restrict__ out){
    extern __shared__ char smem[];
    const uint32_t sb = smem_u32(smem);
    const int b   = blockIdx.y;
    const int row = blockIdx.x;
    const int t   = threadIdx.x;
    const int w   = t >> 5, lane = t & 31;
    const int sub = lane >> 4;
    const int ch  = (lane & 15) * 4;
    const float* xtb = g_xt + (size_t)b*HW*64;
    const float* omb = g_om + (size_t)b*27*HW;

    float d[8][4];
    #pragma unroll
    for (int i = 0; i < 8; ++i)
        #pragma unroll
        for (int k = 0; k < 4; ++k) d[i][k] = 0.f;

    auto gather = [&](int kf, int buf){
        char* sg = smem + buf*DF_STG;
        {
            const __half* src = g_wdc_h + kf*8192;
            #pragma unroll
            for (int p = 0; p < 2; ++p){
                int j = t + p*256;
                int oc = j >> 3, seg = j & 7;
                ((uint4*)(sg + DF_WHI + oc*RSTRIDE + seg*16))[0] = ((const uint4*)src)[j];
                ((uint4*)(sg + DF_WLO + oc*RSTRIDE + seg*16))[0] = ((const uint4*)(src + 4096))[j];
            }
        }
        #pragma unroll 2
        for (int p = 0; p < 8; ++p){
            const int gpx  = p*16 + w*2 + sub;
            const int gpix = row*128 + gpx;
            // bilinear setup (redundant across 16 lanes; omb loads broadcast)
            float offy = omb[(size_t)(2*kf    )*HW + gpix];
            float offx = omb[(size_t)(2*kf + 1)*HW + gpix];
            float m    = omb[(size_t)(18 + kf )*HW + gpix];
            float py = (float)(row + cKY[kf]) + offy;
            float pxf= (float)(gpx + cKX[kf]) + offx;
            float y0f = floorf(py), x0f = floorf(pxf);
            float fy = py - y0f, fx = pxf - x0f;
            int y0 = (int)y0f, x0 = (int)x0f, y1 = y0 + 1, x1 = x0 + 1;
            float vy0 = (y0 >= 0 && y0 <= 127) ? 1.f : 0.f;
            float vy1 = (y1 >= 0 && y1 <= 127) ? 1.f : 0.f;
            float vx0 = (x0 >= 0 && x0 <= 127) ? 1.f : 0.f;
            float vx1 = (x1 >= 0 && x1 <= 127) ? 1.f : 0.f;
            float w00 = (1.f-fy)*(1.f-fx)*vy0*vx0*m;
            float w01 = (1.f-fy)*fx      *vy0*vx1*m;
            float w10 = fy*(1.f-fx)      *vy1*vx0*m;
            float w11 = fy*fx            *vy1*vx1*m;
            int cy0 = min(max(y0,0),127), cy1 = min(max(y1,0),127);
            int cx0 = min(max(x0,0),127), cx1 = min(max(x1,0),127);
            // 4 coalesced corner loads (16 lanes cover 64 ch contiguously)
            float4 v = make_float4(0.f,0.f,0.f,0.f);
            fma4(v, w00, *(const float4*)(xtb + (size_t)(cy0*128 + cx0)*64 + ch));
            fma4(v, w01, *(const float4*)(xtb + (size_t)(cy0*128 + cx1)*64 + ch));
            fma4(v, w10, *(const float4*)(xtb + (size_t)(cy1*128 + cx0)*64 + ch));
            fma4(v, w11, *(const float4*)(xtb + (size_t)(cy1*128 + cx1)*64 + ch));
            float r0,r1,r2,r3;
            uint32_t h0 = pack_hi(v.x, v.y, r0, r1);
            uint32_t h1 = pack_hi(v.z, v.w, r2, r3);
            *(uint2*)(sg + DF_VHI + gpx*RSTRIDE + ch*2) = make_uint2(h0, h1);
            *(uint2*)(sg + DF_VLO + gpx*RSTRIDE + ch*2) = make_uint2(pack_lo(r0,r1), pack_lo(r2,r3));
        }
    };

    gather(0, 0);
    for (int s = 0; s < 9; ++s){
        __syncthreads();
        if (s < 8) gather(s + 1, (s + 1) & 1);
        mma_tap<8>(sb + (s & 1)*DF_STG, DF_VHI, DF_VLO, DF_WHI, DF_WLO,
                   lane, w*16, d);
    }

    const int g  = lane >> 2, t4 = lane & 3;
    float* dstb = out + (size_t)b*64*HW + row*128;
    #pragma unroll
    for (int nc = 0; nc < 8; ++nc){
        int oc0 = 8*nc + 2*t4;
        #pragma unroll
        for (int q = 0; q < 2; ++q){
            int oc = oc0 + q;
            float bv = b_dc[oc];
            dstb[(size_t)oc*HW + w*16 + g]     = d[nc][q]     + bv;
            dstb[(size_t)oc*HW + w*16 + g + 8] = d[nc][q + 2] + bv;
        }
    }
}

// ---------------- launch ----------------
extern "C" void kernel_launch(void* const* d_in, const int* in_sizes, int n_in,
                              void* d_out, int out_size){
    const float* x    = (const float*)d_in[0];
    const float* w_om = (const float*)d_in[1];
    const float* b_om = (const float*)d_in[2];
    const float* w_dc = (const float*)d_in[3];
    const float* b_dc = (const float*)d_in[4];
    float* out = (float*)d_out;

    cudaFuncSetAttribute(conv_om_kernel, cudaFuncAttributeMaxDynamicSharedMemorySize, CV_SMEM);
    cudaFuncSetAttribute(deform_kernel,  cudaFuncAttributeMaxDynamicSharedMemorySize, DF_SMEM);

    prep_kernel<<<216, 256>>>(w_om, w_dc);
    transpose_kernel<<<dim3(256, 8), 256>>>(x);
    conv_om_kernel<<<dim3(128, 8), 256, CV_SMEM>>>(b_om);
    deform_kernel <<<dim3(128, 8), 256, DF_SMEM>>>(b_dc, out);
}

// round 8
// speedup vs baseline: 2.5574x; 1.2818x over previous
#include <cuda_runtime.h>
#include <cuda_fp16.h>
#include <cstdint>

#define HW (128*128)

// ---------------- scratch (no allocations allowed) ----------------
__device__ float  g_om[8*27*HW];          // conv1 out: offsets raw, mask = 2*sigmoid
__device__ float  g_xt[8*HW*64];          // x transposed to NHWC [b][pix][c]
__device__ __half g_wdc_h[9*2*4096];      // [kf][hi/lo][oc(64)][c(64)]
__device__ __half g_wom_h[9*2*2048];      // [kf][hi/lo][oc(32, 27 used)][c(64)]

// ---------------- helpers ----------------
__device__ __forceinline__ uint32_t smem_u32(const void* p){
    uint32_t a;
    asm("{ .reg .u64 t; cvta.to.shared.u64 t, %1; cvt.u32.u64 %0, t; }" : "=r"(a) : "l"(p));
    return a;
}
__device__ __forceinline__ void ldsm_x4(uint32_t &r0,uint32_t &r1,uint32_t &r2,uint32_t &r3, uint32_t addr){
    asm volatile("ldmatrix.sync.aligned.m8n8.x4.shared.b16 {%0,%1,%2,%3}, [%4];"
        : "=r"(r0),"=r"(r1),"=r"(r2),"=r"(r3) : "r"(addr));
}
__device__ __forceinline__ void mma16816(float* d, const uint32_t* a, const uint32_t* b){
    asm volatile("mma.sync.aligned.m16n8k16.row.col.f32.f16.f16.f32 "
        "{%0,%1,%2,%3}, {%4,%5,%6,%7}, {%8,%9}, {%0,%1,%2,%3};"
        : "+f"(d[0]),"+f"(d[1]),"+f"(d[2]),"+f"(d[3])
        : "r"(a[0]),"r"(a[1]),"r"(a[2]),"r"(a[3]), "r"(b[0]),"r"(b[1]));
}
__device__ __forceinline__ uint32_t pack_hi(float a, float b, float &ra, float &rb){
    __half ha = __float2half_rn(a), hb = __float2half_rn(b);
    ra = a - __half2float(ha); rb = b - __half2float(hb);
    __half2 h2 = __halves2half2(ha, hb);
    return *(uint32_t*)&h2;
}
__device__ __forceinline__ uint32_t pack_lo(float ra, float rb){
    __half2 l2 = __floats2half2_rn(ra, rb);
    return *(uint32_t*)&l2;
}
__device__ __forceinline__ void fma4(float4 &acc, float w, float4 p){
    acc.x += w*p.x; acc.y += w*p.y; acc.z += w*p.z; acc.w += w*p.w;
}

__constant__ int cKY[9] = {-1,-1,-1, 0,0,0, 1,1,1};
__constant__ int cKX[9] = {-1, 0, 1,-1,0,1,-1,0,1};

// ---------------- kernel 0: weight split fp32 -> f16 hi/lo ----------------
__global__ void prep_kernel(const float* __restrict__ w_om, const float* __restrict__ w_dc){
    int i = blockIdx.x * blockDim.x + threadIdx.x;
    if (i < 9*4096){
        int kf = i >> 12, rem = i & 4095;
        int oc = rem >> 6, c = rem & 63;
        float w = w_dc[(oc*64 + c)*9 + kf];
        __half hi = __float2half_rn(w);
        __half lo = __float2half_rn(w - __half2float(hi));
        g_wdc_h[kf*8192 + rem]        = hi;
        g_wdc_h[kf*8192 + 4096 + rem] = lo;
    }
    int j = i - 9*4096;
    if (j >= 0 && j < 9*2048){
        int kf = j >> 11, rem = j & 2047;
        int oc = rem >> 6, c = rem & 63;
        float w = (oc < 27) ? w_om[(oc*64 + c)*9 + kf] : 0.f;
        __half hi = __float2half_rn(w);
        __half lo = __float2half_rn(w - __half2float(hi));
        g_wom_h[kf*4096 + rem]        = hi;
        g_wom_h[kf*4096 + 2048 + rem] = lo;
    }
}

// ---------------- kernel 0b: NCHW -> NHWC transpose ----------------
__global__ void __launch_bounds__(256)
transpose_kernel(const float* __restrict__ x){
    __shared__ float tile[64][65];
    const int b   = blockIdx.y;
    const int px0 = blockIdx.x * 64;
    const int t   = threadIdx.x;
    const float* xb = x + (size_t)b*64*HW + px0;
    {
        int cr = t >> 4, pq = t & 15;
        #pragma unroll
        for (int i = 0; i < 4; ++i){
            int c = i*16 + cr;
            float4 v = *(const float4*)(xb + (size_t)c*HW + pq*4);
            tile[c][pq*4+0]=v.x; tile[c][pq*4+1]=v.y;
            tile[c][pq*4+2]=v.z; tile[c][pq*4+3]=v.w;
        }
    }
    __syncthreads();
    {
        int px = t >> 2, cq = t & 3;
        float* ob = g_xt + ((size_t)b*HW + px0 + px)*64 + cq*16;
        #pragma unroll
        for (int i = 0; i < 4; ++i){
            int c = cq*16 + i*4;
            ((float4*)ob)[i] = make_float4(tile[c][px], tile[c+1][px],
                                           tile[c+2][px], tile[c+3][px]);
        }
    }
}

// =====================================================================
// smem geometry: rows padded to 72 halves (144 B), conflict-free ldmatrix
// =====================================================================
#define RSTRIDE 144

#define CV_XHI  0
#define CV_XLO  18432
#define CV_WHI  36864
#define CV_WLO  41472
#define CV_STG  46080
#define CV_SMEM (2*CV_STG)

#define DF_VHI  0
#define DF_VLO  18432
#define DF_WHI  36864
#define DF_WLO  46080
#define DF_STG  55296
#define DF_SMEM (2*DF_STG)

// A = values[128px][64c] hi/lo, B = W[n][64c] hi/lo; B frags via ldsm_x4
template<int NC>
__device__ __forceinline__ void mma_tap(uint32_t stg, int vhi_off, int vlo_off,
                                        int whi_off, int wlo_off,
                                        int lane, int px0, float d[NC][4]){
    const int arow = px0 + (lane & 15);
    const int akof = (lane >> 4) * 16;
    const uint32_t aBaseHi = stg + vhi_off + arow*RSTRIDE + akof;
    const uint32_t aBaseLo = stg + vlo_off + arow*RSTRIDE + akof;
    uint32_t ah[4][4], al[4][4];
    #pragma unroll
    for (int kc = 0; kc < 4; ++kc){
        ldsm_x4(ah[kc][0],ah[kc][1],ah[kc][2],ah[kc][3], aBaseHi + kc*32);
        ldsm_x4(al[kc][0],al[kc][1],al[kc][2],al[kc][3], aBaseLo + kc*32);
    }
    const uint32_t rb = (lane & 7)*RSTRIDE + ((lane >> 3) & 3)*16;
    #pragma unroll
    for (int nc = 0; nc < NC; ++nc){
        uint32_t bh[4][2], bl[4][2];
        const uint32_t bRow = nc*8*RSTRIDE + rb;
        ldsm_x4(bh[0][0],bh[0][1],bh[1][0],bh[1][1], stg + whi_off + bRow);
        ldsm_x4(bh[2][0],bh[2][1],bh[3][0],bh[3][1], stg + whi_off + bRow + 64);
        ldsm_x4(bl[0][0],bl[0][1],bl[1][0],bl[1][1], stg + wlo_off + bRow);
        ldsm_x4(bl[2][0],bl[2][1],bl[3][0],bl[3][1], stg + wlo_off + bRow + 64);
        #pragma unroll
        for (int kc = 0; kc < 4; ++kc){
            mma16816(d[nc], ah[kc], bh[kc]);
            mma16816(d[nc], ah[kc], bl[kc]);
            mma16816(d[nc], al[kc], bh[kc]);
        }
    }
}

// =====================================================================
// kernel 1: 3x3 conv 64->27 (+2*sigmoid) via f16x3 mma.sync
// =====================================================================
__global__ void __launch_bounds__(256, 2)
conv_om_kernel(const float* __restrict__ b_om){
    extern __shared__ char smem[];
    const uint32_t sb = smem_u32(smem);
    const int b   = blockIdx.y;
    const int row = blockIdx.x;
    const int t   = threadIdx.x;
    const int w   = t >> 5, lane = t & 31;
    const int sub = lane >> 4;
    const int ch  = (lane & 15) * 4;
    const float* xtb = g_xt + (size_t)b*HW*64;

    float d[4][4];
    #pragma unroll
    for (int i = 0; i < 4; ++i)
        #pragma unroll
        for (int k = 0; k < 4; ++k) d[i][k] = 0.f;

    auto gather = [&](int kf, int buf){
        char* sg = smem + buf*CV_STG;
        {
            const __half* src = g_wom_h + kf*4096;
            int oc = t >> 3, seg = t & 7;
            ((uint4*)(sg + CV_WHI + oc*RSTRIDE + seg*16))[0] = ((const uint4*)src)[t];
            ((uint4*)(sg + CV_WLO + oc*RSTRIDE + seg*16))[0] = ((const uint4*)(src + 2048))[t];
        }
        const int yy = row + cKY[kf];
        const bool okY = (yy >= 0 && yy < 128);
        #pragma unroll
        for (int p = 0; p < 8; ++p){
            int gpx = p*16 + w*2 + sub;
            int xx = gpx + cKX[kf];
            bool ok = okY && (xx >= 0 && xx < 128);
            float4 v = make_float4(0.f,0.f,0.f,0.f);
            if (ok) v = *(const float4*)(xtb + (size_t)(yy*128 + xx)*64 + ch);
            float r0,r1,r2,r3;
            uint32_t h0 = pack_hi(v.x, v.y, r0, r1);
            uint32_t h1 = pack_hi(v.z, v.w, r2, r3);
            *(uint2*)(sg + CV_XHI + gpx*RSTRIDE + ch*2) = make_uint2(h0, h1);
            *(uint2*)(sg + CV_XLO + gpx*RSTRIDE + ch*2) = make_uint2(pack_lo(r0,r1), pack_lo(r2,r3));
        }
    };

    gather(0, 0);
    for (int s = 0; s < 9; ++s){
        __syncthreads();
        if (s < 8) gather(s + 1, (s + 1) & 1);
        mma_tap<4>(sb + (s & 1)*CV_STG, CV_XHI, CV_XLO, CV_WHI, CV_WLO,
                   lane, w*16, d);
    }

    const int g  = lane >> 2, t4 = lane & 3;
    float* dstb = g_om + (size_t)b*27*HW + row*128;
    #pragma unroll
    for (int nc = 0; nc < 4; ++nc){
        int oc0 = 8*nc + 2*t4;
        #pragma unroll
        for (int q = 0; q < 2; ++q){
            int oc = oc0 + q;
            if (oc >= 27) continue;
            float bv = b_om[oc];
            float v0 = d[nc][q]     + bv;
            float v1 = d[nc][q + 2] + bv;
            if (oc >= 18){
                v0 = 2.f/(1.f + __expf(-v0));
                v1 = 2.f/(1.f + __expf(-v1));
            }
            dstb[(size_t)oc*HW + w*16 + g]     = v0;
            dstb[(size_t)oc*HW + w*16 + g + 8] = v1;
        }
    }
}

// =====================================================================
// kernel 2: deformable conv 64->64 via f16x3 mma.sync
// setup dedup: lanes 0-15 each own one of the warp's 16 pixels;
// gather broadcasts setup via shfl. Offset loads pipelined 2 taps ahead.
// =====================================================================
__global__ void __launch_bounds__(256, 2)
deform_kernel(const float* __restrict__ b_dc, float* __restrict__ out){
    extern __shared__ char smem[];
    const uint32_t sb = smem_u32(smem);
    const int b   = blockIdx.y;
    const int row = blockIdx.x;
    const int t   = threadIdx.x;
    const int w   = t >> 5, lane = t & 31;
    const int sub = lane >> 4;
    const int ch  = (lane & 15) * 4;
    const float* xtb = g_xt + (size_t)b*HW*64;
    const float* omb = g_om + (size_t)b*27*HW;

    // setup-owner pixel for this lane: sl = lane&15 -> (psub = sl>>3, p = sl&7)
    const int sl   = lane & 15;
    const int sgpx = (sl & 7)*16 + w*2 + (sl >> 3);
    const int sgpix = row*128 + sgpx;

    float d[8][4];
    #pragma unroll
    for (int i = 0; i < 8; ++i)
        #pragma unroll
        for (int k = 0; k < 4; ++k) d[i][k] = 0.f;

    float sw00, sw01, sw10, sw11;          // my pixel's setup
    int   si00, si01, si10, si11;
    float poy, pox, pom;                    // pending omb (next tap to set up)

    auto load_omb = [&](int kf){
        poy = omb[(size_t)(2*kf    )*HW + sgpix];
        pox = omb[(size_t)(2*kf + 1)*HW + sgpix];
        pom = omb[(size_t)(18 + kf )*HW + sgpix];
    };
    auto comp_setup = [&](int kf){
        float py  = (float)(row  + cKY[kf]) + poy;
        float pxf = (float)(sgpx + cKX[kf]) + pox;
        float y0f = floorf(py), x0f = floorf(pxf);
        float fy = py - y0f, fx = pxf - x0f;
        int y0 = (int)y0f, x0 = (int)x0f, y1 = y0 + 1, x1 = x0 + 1;
        float vy0 = (y0 >= 0 && y0 <= 127) ? 1.f : 0.f;
        float vy1 = (y1 >= 0 && y1 <= 127) ? 1.f : 0.f;
        float vx0 = (x0 >= 0 && x0 <= 127) ? 1.f : 0.f;
        float vx1 = (x1 >= 0 && x1 <= 127) ? 1.f : 0.f;
        sw00 = (1.f-fy)*(1.f-fx)*vy0*vx0*pom;
        sw01 = (1.f-fy)*fx      *vy0*vx1*pom;
        sw10 = fy*(1.f-fx)      *vy1*vx0*pom;
        sw11 = fy*fx            *vy1*vx1*pom;
        int cy0 = min(max(y0,0),127), cy1 = min(max(y1,0),127);
        int cx0 = min(max(x0,0),127), cx1 = min(max(x1,0),127);
        si00 = cy0*128 + cx0; si01 = cy0*128 + cx1;
        si10 = cy1*128 + cx0; si11 = cy1*128 + cx1;
    };
    auto gather = [&](int kf, int buf){
        char* sg = smem + buf*DF_STG;
        {
            const __half* src = g_wdc_h + kf*8192;
            #pragma unroll
            for (int p = 0; p < 2; ++p){
                int j = t + p*256;
                int oc = j >> 3, seg = j & 7;
                ((uint4*)(sg + DF_WHI + oc*RSTRIDE + seg*16))[0] = ((const uint4*)src)[j];
                ((uint4*)(sg + DF_WLO + oc*RSTRIDE + seg*16))[0] = ((const uint4*)(src + 4096))[j];
            }
        }
        #pragma unroll
        for (int p = 0; p < 8; ++p){
            const int src = sub*8 + p;        // lane holding this pixel's setup
            float w00 = __shfl_sync(0xffffffffu, sw00, src);
            float w01 = __shfl_sync(0xffffffffu, sw01, src);
            float w10 = __shfl_sync(0xffffffffu, sw10, src);
            float w11 = __shfl_sync(0xffffffffu, sw11, src);
            int   i00 = __shfl_sync(0xffffffffu, si00, src);
            int   i01 = __shfl_sync(0xffffffffu, si01, src);
            int   i10 = __shfl_sync(0xffffffffu, si10, src);
            int   i11 = __shfl_sync(0xffffffffu, si11, src);
            const int gpx = p*16 + w*2 + sub;
            float4 v = make_float4(0.f,0.f,0.f,0.f);
            fma4(v, w00, *(const float4*)(xtb + (size_t)i00*64 + ch));
            fma4(v, w01, *(const float4*)(xtb + (size_t)i01*64 + ch));
            fma4(v, w10, *(const float4*)(xtb + (size_t)i10*64 + ch));
            fma4(v, w11, *(const float4*)(xtb + (size_t)i11*64 + ch));
            float r0,r1,r2,r3;
            uint32_t h0 = pack_hi(v.x, v.y, r0, r1);
            uint32_t h1 = pack_hi(v.z, v.w, r2, r3);
            *(uint2*)(sg + DF_VHI + gpx*RSTRIDE + ch*2) = make_uint2(h0, h1);
            *(uint2*)(sg + DF_VLO + gpx*RSTRIDE + ch*2) = make_uint2(pack_lo(r0,r1), pack_lo(r2,r3));
        }
    };

    // prologue: setup tap 0, gather tap 0, preload omb for tap 1
    load_omb(0);
    comp_setup(0);
    load_omb(1);
    gather(0, 0);

    for (int s = 0; s < 9; ++s){
        __syncthreads();
        if (s < 8){
            comp_setup(s + 1);              // from regs loaded 1 tap ago
            if (s < 7) load_omb(s + 2);     // hidden under this tap's work
            gather(s + 1, (s + 1) & 1);
        }
        mma_tap<8>(sb + (s & 1)*DF_STG, DF_VHI, DF_VLO, DF_WHI, DF_WLO,
                   lane, w*16, d);
    }

    const int g  = lane >> 2, t4 = lane & 3;
    float* dstb = out + (size_t)b*64*HW + row*128;
    #pragma unroll
    for (int nc = 0; nc < 8; ++nc){
        int oc0 = 8*nc + 2*t4;
        #pragma unroll
        for (int q = 0; q < 2; ++q){
            int oc = oc0 + q;
            float bv = b_dc[oc];
            dstb[(size_t)oc*HW + w*16 + g]     = d[nc][q]     + bv;
            dstb[(size_t)oc*HW + w*16 + g + 8] = d[nc][q + 2] + bv;
        }
    }
}

// ---------------- launch ----------------
extern "C" void kernel_launch(void* const* d_in, const int* in_sizes, int n_in,
                              void* d_out, int out_size){
    const float* x    = (const float*)d_in[0];
    const float* w_om = (const float*)d_in[1];
    const float* b_om = (const float*)d_in[2];
    const float* w_dc = (const float*)d_in[3];
    const float* b_dc = (const float*)d_in[4];
    float* out = (float*)d_out;

    cudaFuncSetAttribute(conv_om_kernel, cudaFuncAttributeMaxDynamicSharedMemorySize, CV_SMEM);
    cudaFuncSetAttribute(deform_kernel,  cudaFuncAttributeMaxDynamicSharedMemorySize, DF_SMEM);

    prep_kernel<<<216, 256>>>(w_om, w_dc);
    transpose_kernel<<<dim3(256, 8), 256>>>(x);
    conv_om_kernel<<<dim3(128, 8), 256, CV_SMEM>>>(b_om);
    deform_kernel <<<dim3(128, 8), 256, DF_SMEM>>>(b_dc, out);
}